// round 3
// baseline (speedup 1.0000x reference)
#include <cuda_runtime.h>
#include <stdint.h>

// Fp8Unpadding: gather un-padded rows out of a 256-row-padded concatenation.
// M_SPLITS = {1000,2300,512,3777,129,2048,900,1500}, HIDDEN=4096 (f32).
// dst row r maps to src row r + DELTA[group(r)]; DELTA constant per group.
//
// Row boundaries (cumulative m):  1000, 3300, 3812, 7589, 7718, 9766, 10666, 12166
// Row deltas:                        0,   24,   28,   28,   91,  218,   218,   342
//
// R3: persistent grid-stride kernel (1184 CTAs = 148 SM x 8), 8x float4 per
// chunk iteration, front-batched loads (MLP=8), streaming cache hints.
// Removes wave transitions / launch ramp of the 6083-CTA one-shot version.

static constexpr int HIDDEN_V4  = 4096 / 4;                 // 1024
static constexpr int TOTAL_ROWS = 12166;
static constexpr int TOTAL_V4   = TOTAL_ROWS * HIDDEN_V4;   // 12,457,984
static constexpr int UNROLL     = 8;
static constexpr int TPB        = 256;
static constexpr int CHUNK      = TPB * UNROLL;             // 2048
static constexpr int NCHUNKS    = TOTAL_V4 / CHUNK;         // 6083 (exact)
static constexpr int NCTAS      = 148 * 8;                  // 1184 persistent CTAs

__device__ __forceinline__ int row_delta(int row)
{
    return (row < 1000)  ? 0
         : (row < 3300)  ? 24
         : (row < 7589)  ? 28
         : (row < 7718)  ? 91
         : (row < 10666) ? 218
         :                 342;
}

__global__ void __launch_bounds__(TPB)
unpad_gather_kernel(const float4* __restrict__ in, float4* __restrict__ out)
{
    for (int c = blockIdx.x; c < NCHUNKS; c += NCTAS) {
        int base = c * CHUNK + threadIdx.x;

        float4 v[UNROLL];

        // front-batched independent loads (deep MLP)
        #pragma unroll
        for (int j = 0; j < UNROLL; j++) {
            int i = base + j * TPB;
            int d = row_delta(i >> 10);
            v[j] = __ldcs(in + i + d * HIDDEN_V4);
        }

        #pragma unroll
        for (int j = 0; j < UNROLL; j++) {
            __stcs(out + base + j * TPB, v[j]);
        }
    }
}

extern "C" void kernel_launch(void* const* d_in, const int* in_sizes, int n_in,
                              void* d_out, int out_size)
{
    const float4* in  = (const float4*)d_in[0];   // f32 [12544, 4096]
    float4*       out = (float4*)d_out;           // f32 [12166, 4096]

    unpad_gather_kernel<<<NCTAS, TPB>>>(in, out);
}